// round 2
// baseline (speedup 1.0000x reference)
#include <cuda_runtime.h>
#include <math_constants.h>

#define BB 32
#define SS 2048
#define DD 512
#define CC 2
#define NSPLIT 16
#define TOK_PER_SPLIT (SS / NSPLIT)   // 128
#define WARPS 8
#define NTHREADS (WARPS * 32)

// scratch: per (batch, split): [m, l, acc[512]]
__device__ float g_partial[BB * NSPLIT * (DD + 2)];
__device__ int   g_tok_is_i32;

// ---------------------------------------------------------------------------
// Kernel 0: detect token dtype. int64 tokens in [0,32000) have all-zero high
// words; 64 random int32 tokens cannot all be zero at odd word positions.
// ---------------------------------------------------------------------------
__global__ void detect_tok_kernel(const void* __restrict__ tokens) {
    const int* w = (const int*)tokens;
    int any = 0;
    #pragma unroll
    for (int i = 1; i < 128; i += 2) any |= (w[i] != 0);
    g_tok_is_i32 = any ? 1 : 0;
}

// ---------------------------------------------------------------------------
// Kernel 1: split-K single-query flash attention.
// grid = (NSPLIT, BB), block = 256. Each warp processes one token row at a
// time: 4x float4 coalesced load, warp-shuffle dot vs q, online softmax
// accumulate into a 16-float/lane register accumulator.
// ---------------------------------------------------------------------------
__global__ __launch_bounds__(NTHREADS) void attn_partial_kernel(
    const void* __restrict__ tokens, const float* __restrict__ emb)
{
    const int split = blockIdx.x;
    const int b     = blockIdx.y;
    const int warp  = threadIdx.x >> 5;
    const int lane  = threadIdx.x & 31;

    const bool i32 = (g_tok_is_i32 != 0);
    const int*       t32 = (const int*)tokens + (size_t)b * SS;
    const long long* t64 = (const long long*)tokens + (size_t)b * SS;

    // q = emb[tokens[b,0]]  (register fragment: 16 floats/lane)
    long long q_idx = i32 ? (long long)t32[0] : t64[0];
    const float4* qrow = (const float4*)(emb + q_idx * DD);
    float4 q[4];
    #pragma unroll
    for (int k = 0; k < 4; k++) q[k] = __ldg(&qrow[lane + k * 32]);

    float m = -CUDART_INF_F;
    float l = 0.0f;
    float4 acc[4];
    #pragma unroll
    for (int k = 0; k < 4; k++) acc[k] = make_float4(0.f, 0.f, 0.f, 0.f);

    const int t0 = split * TOK_PER_SPLIT;
    for (int j = warp; j < TOK_PER_SPLIT; j += WARPS) {
        const int t = t0 + j;
        long long idx = i32 ? (long long)t32[t] : t64[t];
        const float4* row = (const float4*)(emb + idx * DD);
        float4 r[4];
        #pragma unroll
        for (int k = 0; k < 4; k++) r[k] = __ldg(&row[lane + k * 32]);

        float s = 0.0f;
        #pragma unroll
        for (int k = 0; k < 4; k++) {
            s += r[k].x * q[k].x + r[k].y * q[k].y
               + r[k].z * q[k].z + r[k].w * q[k].w;
        }
        #pragma unroll
        for (int o = 16; o > 0; o >>= 1) s += __shfl_xor_sync(0xffffffffu, s, o);

        const float m_new = fmaxf(m, s);
        const float fac   = expf(m - m_new);   // exp(-inf)=0 handles first iter
        const float w     = expf(s - m_new);
        l = l * fac + w;
        #pragma unroll
        for (int k = 0; k < 4; k++) {
            acc[k].x = acc[k].x * fac + w * r[k].x;
            acc[k].y = acc[k].y * fac + w * r[k].y;
            acc[k].z = acc[k].z * fac + w * r[k].z;
            acc[k].w = acc[k].w * fac + w * r[k].w;
        }
        m = m_new;
    }

    // --- combine the 8 warps' partials inside the CTA ---
    __shared__ float sh_m[WARPS];
    __shared__ float sh_l[WARPS];
    __shared__ float sh_acc[WARPS][DD];   // 16 KB

    if (lane == 0) { sh_m[warp] = m; sh_l[warp] = l; }
    #pragma unroll
    for (int k = 0; k < 4; k++) {
        const int base = k * 128 + lane * 4;
        sh_acc[warp][base + 0] = acc[k].x;
        sh_acc[warp][base + 1] = acc[k].y;
        sh_acc[warp][base + 2] = acc[k].z;
        sh_acc[warp][base + 3] = acc[k].w;
    }
    __syncthreads();

    float M = sh_m[0];
    #pragma unroll
    for (int w2 = 1; w2 < WARPS; w2++) M = fmaxf(M, sh_m[w2]);
    float facw[WARPS];
    float L = 0.0f;
    #pragma unroll
    for (int w2 = 0; w2 < WARPS; w2++) {
        facw[w2] = expf(sh_m[w2] - M);
        L += sh_l[w2] * facw[w2];
    }

    float* outp = &g_partial[(b * NSPLIT + split) * (DD + 2)];
    for (int d = threadIdx.x; d < DD; d += NTHREADS) {
        float v = 0.0f;
        #pragma unroll
        for (int w2 = 0; w2 < WARPS; w2++) v += sh_acc[w2][d] * facw[w2];
        outp[2 + d] = v;
    }
    if (threadIdx.x == 0) { outp[0] = M; outp[1] = L; }
}

// ---------------------------------------------------------------------------
// Kernel 2: combine the NSPLIT partials per batch + classifier head.
// grid = BB, block = 256.
// ---------------------------------------------------------------------------
__global__ __launch_bounds__(256) void reduce_head_kernel(
    const float* __restrict__ cls_w, const float* __restrict__ cls_b,
    float* __restrict__ out)
{
    const int b = blockIdx.x;
    const float* base = &g_partial[b * NSPLIT * (DD + 2)];
    const int warp = threadIdx.x >> 5;
    const int lane = threadIdx.x & 31;

    __shared__ float sh_ms[NSPLIT];
    __shared__ float sh_ls[NSPLIT];
    if (threadIdx.x < NSPLIT) {
        sh_ms[threadIdx.x] = base[threadIdx.x * (DD + 2) + 0];
        sh_ls[threadIdx.x] = base[threadIdx.x * (DD + 2) + 1];
    }
    __syncthreads();

    float M = sh_ms[0];
    #pragma unroll
    for (int s = 1; s < NSPLIT; s++) M = fmaxf(M, sh_ms[s]);
    float f[NSPLIT];
    float L = 0.0f;
    #pragma unroll
    for (int s = 0; s < NSPLIT; s++) {
        f[s] = expf(sh_ms[s] - M);
        L += sh_ls[s] * f[s];
    }
    const float invL = 1.0f / L;

    float pd0 = 0.0f, pd1 = 0.0f;
    for (int d = threadIdx.x; d < DD; d += 256) {
        float v = 0.0f;
        #pragma unroll
        for (int s = 0; s < NSPLIT; s++) v += base[s * (DD + 2) + 2 + d] * f[s];
        v *= invL;
        pd0 += v * __ldg(&cls_w[0 * DD + d]);
        pd1 += v * __ldg(&cls_w[1 * DD + d]);
    }
    #pragma unroll
    for (int o = 16; o > 0; o >>= 1) {
        pd0 += __shfl_xor_sync(0xffffffffu, pd0, o);
        pd1 += __shfl_xor_sync(0xffffffffu, pd1, o);
    }
    __shared__ float rw0[8];
    __shared__ float rw1[8];
    if (lane == 0) { rw0[warp] = pd0; rw1[warp] = pd1; }
    __syncthreads();
    if (threadIdx.x == 0) {
        float s0 = 0.0f, s1 = 0.0f;
        #pragma unroll
        for (int w2 = 0; w2 < 8; w2++) { s0 += rw0[w2]; s1 += rw1[w2]; }
        out[b * CC + 0] = s0 + __ldg(&cls_b[0]);
        out[b * CC + 1] = s1 + __ldg(&cls_b[1]);
    }
}

// ---------------------------------------------------------------------------
extern "C" void kernel_launch(void* const* d_in, const int* in_sizes, int n_in,
                              void* d_out, int out_size) {
    (void)in_sizes; (void)n_in; (void)out_size;
    const void*  tokens = d_in[0];
    const float* emb    = (const float*)d_in[1];
    const float* cls_w  = (const float*)d_in[2];
    const float* cls_b  = (const float*)d_in[3];
    float* out = (float*)d_out;

    detect_tok_kernel<<<1, 1>>>(tokens);
    dim3 grid(NSPLIT, BB);
    attn_partial_kernel<<<grid, NTHREADS>>>(tokens, emb);
    reduce_head_kernel<<<BB, 256>>>(cls_w, cls_b, out);
}